// round 15
// baseline (speedup 1.0000x reference)
#include <cuda_runtime.h>
#include <cstdint>
#include <cstddef>

// LowRankINRLayer: out = relu( (x @ v^T) @ W^T )
//   x [16,8192,512] f32, v [16,32,512] f32, W [512,32] f32 -> out f32
//
// Round 15: split-K tiles to fix wave quantization. Tile = 64 rows; warps 0-3
// reduce K[0:256], warps 4-7 K[256:512] (same mma/ldsm body as R12), halves
// summed in f32 via smem before the R12 staged-STG.128 epilogue. 2048 tiles /
// 296 slots -> W=6.92 (98.8% wave util vs 86.5% at W=3.46). 4-stage cp.async,
// 110.6KB smem, 2 CTAs/SM, prep-blocked tf32 v, W register-resident.

namespace {

constexpr int kB  = 16;
constexpr int kN  = 8192;
constexpr int kDI = 512;
constexpr int kDO = 512;
constexpr int kR  = 32;

constexpr int TM      = 64;           // rows per tile
constexpr int KC      = 32;           // K per chunk per group
constexpr int NCH     = 8;            // chunks per group (K/2 / KC)
constexpr int STAGES  = 4;
constexpr int THREADS = 256;          // 8 warps = 2 groups x 4

constexpr int XW   = KC + 4;                       // 36 words row stride (144B)
constexpr int XBUF = TM * XW;                      // 2304 words / stage / half
constexpr int VBUF = kR * XW;                      // 1152 words / stage / half
constexpr int X1_OFF = STAGES * XBUF;              // 9216
constexpr int V0_OFF = 2 * STAGES * XBUF;          // 18432
constexpr int V1_OFF = V0_OFF + STAGES * VBUF;     // 23040
constexpr int SMEM_WORDS = V1_OFF + STAGES * VBUF; // 27648
constexpr int SMEM_BYTES = SMEM_WORDS * 4;         // 110592 B -> 2 CTAs/SM

// post-mainloop reuse: C1a at word 0, C1b at 4608 (X0 region, 9216 words);
// staging in X1 region (9216 words >= 8*1024)
constexpr int C1B_OFF = TM * XW;                   // 2304*2? no: 64*36 = 2304
constexpr int STG_OFF = X1_OFF;                    // word 9216
constexpr int STG_PER_WARP = 16 * 64;              // 1024 words

// tf32(RNA) scratch, filled by prep kernel: blocked [b][ck][n][kk], ck<16
__device__ unsigned g_v[kB * kR * kDI];

__device__ __forceinline__ unsigned f2tf(float f) {
    unsigned u;
    asm("cvt.rna.tf32.f32 %0, %1;" : "=r"(u) : "f"(f));
    return u;
}
__device__ __forceinline__ unsigned f2tf_u(unsigned raw) {
    return f2tf(__uint_as_float(raw));
}

__device__ __forceinline__ void ldsm4(unsigned& r0, unsigned& r1,
                                      unsigned& r2, unsigned& r3, unsigned a) {
    asm volatile("ldmatrix.sync.aligned.m8n8.x4.shared.b16 {%0,%1,%2,%3}, [%4];"
                 : "=r"(r0), "=r"(r1), "=r"(r2), "=r"(r3) : "r"(a));
}

__device__ __forceinline__ void mma_tf32(float& d0, float& d1, float& d2, float& d3,
                                         unsigned a0, unsigned a1, unsigned a2, unsigned a3,
                                         unsigned b0, unsigned b1) {
    asm volatile(
        "mma.sync.aligned.m16n8k8.row.col.f32.tf32.tf32.f32 "
        "{%0,%1,%2,%3}, {%4,%5,%6,%7}, {%8,%9}, {%0,%1,%2,%3};"
        : "+f"(d0), "+f"(d1), "+f"(d2), "+f"(d3)
        : "r"(a0), "r"(a1), "r"(a2), "r"(a3), "r"(b0), "r"(b1));
}

__device__ __forceinline__ void cp16(unsigned dst_smem, const void* src) {
    asm volatile("cp.async.cg.shared.global [%0], [%1], 16;"
                 :: "r"(dst_smem), "l"(src) : "memory");
}

// ---- prep: v -> tf32 RNA blocked [b][ck][n][kk], vectorized float4 ----
__global__ void __launch_bounds__(256, 4) prep_kernel(const float* __restrict__ v) {
    const int base = blockIdx.x * 256 + threadIdx.x;
    float4 in0 = *reinterpret_cast<const float4*>(v + 4 * (size_t)base);
    float4 in1 = *reinterpret_cast<const float4*>(v + 4 * (size_t)(base + 32768));
    #pragma unroll
    for (int i = 0; i < 2; i++) {
        const int f4 = base + i * 32768;
        const int e  = f4 * 4;
        const int b  = e >> 14, rem = e & 16383;
        const int n  = rem >> 9, k = rem & 511;
        const int ck = k >> 5, kk = k & 31;
        const float4 in = i ? in1 : in0;
        uint4 o = make_uint4(f2tf(in.x), f2tf(in.y), f2tf(in.z), f2tf(in.w));
        *reinterpret_cast<uint4*>(&g_v[(b << 14) + (ck << 10) + (n << 5) + kk]) = o;
    }
}

__global__ void __launch_bounds__(THREADS, 2)
lowrank_kernel(const float* __restrict__ x,
               const float* __restrict__ W,
               float* __restrict__ out)
{
    extern __shared__ unsigned smu[];
    const unsigned sbase = (unsigned)__cvta_generic_to_shared(smu);

    const int tid  = threadIdx.x;
    const int lane = tid & 31;
    const int warp = tid >> 5;
    const int grp  = warp >> 2;           // 0: K[0:256], 1: K[256:512]
    const int wg   = warp & 3;
    const int g    = lane >> 2;
    const int t4   = lane & 3;
    const int mw   = wg * 16;             // rows within 64-row tile

    const int b  = blockIdx.x >> 7;       // 128 tiles of 64 rows per batch
    const int m0 = (blockIdx.x & 127) * TM;

    const float*    xg  = x + ((size_t)b * kN + m0) * kDI;
    const unsigned* gvb = g_v + (size_t)b * (kR * kDI);

    const int vr = tid >> 3, vu = tid & 7;   // v: 256 x 16B units per half

    auto issue = [&](int c) {
        const int s = c & (STAGES - 1);
        // x low half: 512 units (64 rows x 8), 2 per thread
        #pragma unroll
        for (int i = 0; i < 2; i++) {
            const int q = tid + 256 * i;
            const int r = q >> 3, u = q & 7;
            cp16(sbase + (unsigned)(s * XBUF + r * XW + u * 4) * 4u,
                 xg + (size_t)r * kDI + c * KC + u * 4);
        }
        // x high half
        #pragma unroll
        for (int i = 0; i < 2; i++) {
            const int q = tid + 256 * i;
            const int r = q >> 3, u = q & 7;
            cp16(sbase + (unsigned)(X1_OFF + s * XBUF + r * XW + u * 4) * 4u,
                 xg + (size_t)r * kDI + 256 + c * KC + u * 4);
        }
        // v halves: ck = c and ck = 8 + c (blocked layout, 32 words/row)
        cp16(sbase + (unsigned)(V0_OFF + s * VBUF + vr * XW + vu * 4) * 4u,
             gvb + c * 1024 + vr * 32 + vu * 4);
        cp16(sbase + (unsigned)(V1_OFF + s * VBUF + vr * XW + vu * 4) * 4u,
             gvb + (8 + c) * 1024 + vr * 32 + vu * 4);
        asm volatile("cp.async.commit_group;" ::: "memory");
    };

    issue(0); issue(1); issue(2);

    // ldmatrix per-lane byte offsets within this group's stage buffers
    const unsigned a_boff = (unsigned)(mw + (lane & 15)) * 144u
                          + (unsigned)((lane >> 4) * 16);
    const unsigned b_boff = (unsigned)(((lane >> 4) << 3) + (lane & 7)) * 144u
                          + (unsigned)(((lane >> 3) & 1) * 16);
    const unsigned xg_off = (unsigned)(grp ? X1_OFF : 0) * 4u;
    const unsigned vg_off = (unsigned)(grp ? V1_OFF : V0_OFF) * 4u;

    // ---- GEMM1 mainloop: per warp m=16, n=32, k=256 (its K half) ----
    float acc[4][4] = {};

    for (int c = 0; c < NCH; ++c) {
        if (c < NCH - 2)        asm volatile("cp.async.wait_group 2;" ::: "memory");
        else if (c == NCH - 2)  asm volatile("cp.async.wait_group 1;" ::: "memory");
        else                    asm volatile("cp.async.wait_group 0;" ::: "memory");
        __syncthreads();   // chunk c ready; chunk c-1 consumed by all warps

        if (c + 3 < NCH) issue(c + 3);

        const unsigned xa = sbase + xg_off + (unsigned)((c & 3) * XBUF) * 4u + a_boff;
        const unsigned vb = sbase + vg_off + (unsigned)((c & 3) * VBUF) * 4u + b_boff;

        #pragma unroll
        for (int ks = 0; ks < 4; ks++) {
            unsigned ra0, ra1, ra2, ra3;
            ldsm4(ra0, ra1, ra2, ra3, xa + 32u * ks);
            unsigned a0 = f2tf_u(ra0), a1 = f2tf_u(ra1);
            unsigned a2 = f2tf_u(ra2), a3 = f2tf_u(ra3);
            #pragma unroll
            for (int nbp = 0; nbp < 2; nbp++) {
                unsigned b00, b01, b10, b11;
                ldsm4(b00, b01, b10, b11, vb + (unsigned)(nbp * 2304) + 32u * ks);
                mma_tf32(acc[2*nbp][0],   acc[2*nbp][1],   acc[2*nbp][2],   acc[2*nbp][3],
                         a0, a1, a2, a3, b00, b01);
                mma_tf32(acc[2*nbp+1][0], acc[2*nbp+1][1], acc[2*nbp+1][2], acc[2*nbp+1][3],
                         a0, a1, a2, a3, b10, b11);
            }
        }
    }

    // ---- store both K-half partials (64x32 each) into X0 region ----
    __syncthreads();
    float* chalf = (float*)smu + grp * C1B_OFF;   // C1a at 0, C1b at 2304
    #pragma unroll
    for (int nb = 0; nb < 4; nb++) {
        *reinterpret_cast<float2*>(&chalf[(mw + g)     * XW + nb * 8 + 2 * t4]) =
            make_float2(acc[nb][0], acc[nb][1]);
        *reinterpret_cast<float2*>(&chalf[(mw + g + 8) * XW + nb * 8 + 2 * t4]) =
            make_float2(acc[nb][2], acc[nb][3]);
    }
    __syncthreads();

    // ---- GEMM2: relu((C1a+C1b) @ W^T); warp owns o-cols [warp*64,+64) ----
    const int oc0 = warp * 64;
    unsigned wf[8][4][2];
    #pragma unroll
    for (int ob = 0; ob < 8; ob++) {
        const float* wr = W + (size_t)(oc0 + ob * 8 + g) * kR;
        #pragma unroll
        for (int ks = 0; ks < 4; ks++) {
            wf[ob][ks][0] = f2tf(wr[ks * 8 + t4]);
            wf[ob][ks][1] = f2tf(wr[ks * 8 + t4 + 4]);
        }
    }

    const float* c1a = (const float*)smu;
    const float* c1b = (const float*)smu + C1B_OFF;
    float* stg = (float*)smu + STG_OFF + warp * STG_PER_WARP;
    float* ob_ = out + ((size_t)b * kN + m0) * kDO;

    #pragma unroll 1
    for (int mb = 0; mb < TM / 16; mb++) {
        const int r0 = mb * 16 + g;
        unsigned a[4][4];
        #pragma unroll
        for (int ks = 0; ks < 4; ks++) {
            const int i0 = r0       * XW + ks * 8 + t4;
            const int i1 = (r0 + 8) * XW + ks * 8 + t4;
            a[ks][0] = f2tf(c1a[i0]     + c1b[i0]);
            a[ks][1] = f2tf(c1a[i1]     + c1b[i1]);
            a[ks][2] = f2tf(c1a[i0 + 4] + c1b[i0 + 4]);
            a[ks][3] = f2tf(c1a[i1 + 4] + c1b[i1 + 4]);
        }
        const int sw = (g & 3) << 3;
        #pragma unroll
        for (int ob = 0; ob < 8; ob++) {
            float d0 = 0.f, d1 = 0.f, d2 = 0.f, d3 = 0.f;
            #pragma unroll
            for (int ks = 0; ks < 4; ks++)
                mma_tf32(d0, d1, d2, d3,
                         a[ks][0], a[ks][1], a[ks][2], a[ks][3],
                         wf[ob][ks][0], wf[ob][ks][1]);
            const int lc = (ob * 8 + 2 * t4) ^ sw;
            *reinterpret_cast<float2*>(&stg[g * 64 + lc]) =
                make_float2(fmaxf(d0, 0.f), fmaxf(d1, 0.f));
            *reinterpret_cast<float2*>(&stg[(g + 8) * 64 + lc]) =
                make_float2(fmaxf(d2, 0.f), fmaxf(d3, 0.f));
        }
        __syncwarp();
        const int half = lane >> 4;
        const int colw = (lane & 15) * 4;
        #pragma unroll
        for (int i = 0; i < 8; i++) {
            const int row = 2 * i + half;
            const int sc  = colw ^ ((row & 3) << 3);
            float4 val = *reinterpret_cast<float4*>(&stg[row * 64 + sc]);
            *reinterpret_cast<float4*>(
                &ob_[(size_t)(mb * 16 + row) * kDO + oc0 + colw]) = val;
        }
        __syncwarp();
    }
}

} // namespace

extern "C" void kernel_launch(void* const* d_in, const int* in_sizes, int n_in,
                              void* d_out, int out_size) {
    (void)in_sizes; (void)n_in; (void)out_size;
    const float* x = (const float*)d_in[0];
    const float* v = (const float*)d_in[1];
    const float* W = (const float*)d_in[2];
    float* out = (float*)d_out;

    prep_kernel<<<128, 256>>>(v);

    cudaFuncSetAttribute(lowrank_kernel,
                         cudaFuncAttributeMaxDynamicSharedMemorySize, SMEM_BYTES);
    lowrank_kernel<<<kB * (kN / TM), THREADS, SMEM_BYTES>>>(x, W, out);
}

// round 16
// speedup vs baseline: 1.1555x; 1.1555x over previous
#include <cuda_runtime.h>
#include <cstdint>
#include <cstddef>

// LowRankINRLayer: out = relu( (x @ v^T) @ W^T )
//   x [16,8192,512] f32, v [16,32,512] f32, W [512,32] f32 -> out f32
//
// Round 16: R14 (tf32 mma.sync, 4-stage cp.async KC=32, TM=128, 256 thr,
// 92KB smem, 2 CTAs/SM, ldmatrix fragments, prep-blocked tf32 v, W register-
// resident, staged STG.128 epilogue) with the mainloop processing TWO chunks
// per synchronization cycle: 8 waits instead of 16, deeper prologue (4 chunks),
// back-to-back 2-chunk compute spans. Addressing/numerics identical to R14.

namespace {

constexpr int kB  = 16;
constexpr int kN  = 8192;
constexpr int kDI = 512;
constexpr int kDO = 512;
constexpr int kR  = 32;

constexpr int TM      = 128;          // rows per CTA
constexpr int KC      = 32;           // K per pipeline chunk
constexpr int NCH     = kDI / KC;     // 16
constexpr int STAGES  = 4;
constexpr int THREADS = 256;          // 8 warps

constexpr int XW = KC + 4;                          // 36 words row stride (144 B)
constexpr int XBUF = TM * XW;                       // 4608 words / stage
constexpr int VBUF = kR * XW;                       // 1152 words / stage
constexpr int V_OFF = STAGES * XBUF;                // 18432
constexpr int SMEM_WORDS = V_OFF + STAGES * VBUF;   // 23040
constexpr int SMEM_BYTES = SMEM_WORDS * 4;          // 92160 B -> 2 CTAs/SM

// epilogue staging: warp-private 16 rows x 64 words, inside stage-1..3 region
constexpr int STG_OFF = XBUF;                       // word 4608 (stage 1 start)
constexpr int STG_PER_WARP = 16 * 64;               // 1024 words (4 KB)

// tf32(RNA) scratch, filled by prep kernel
__device__ unsigned g_v[kB * kR * kDI];   // blocked [b][ck][n][kk], kk<32

__device__ __forceinline__ unsigned f2tf(float f) {
    unsigned u;
    asm("cvt.rna.tf32.f32 %0, %1;" : "=r"(u) : "f"(f));
    return u;
}
__device__ __forceinline__ unsigned f2tf_u(unsigned raw) {
    return f2tf(__uint_as_float(raw));
}

__device__ __forceinline__ void ldsm4(unsigned& r0, unsigned& r1,
                                      unsigned& r2, unsigned& r3, unsigned a) {
    asm volatile("ldmatrix.sync.aligned.m8n8.x4.shared.b16 {%0,%1,%2,%3}, [%4];"
                 : "=r"(r0), "=r"(r1), "=r"(r2), "=r"(r3) : "r"(a));
}

__device__ __forceinline__ void mma_tf32(float& d0, float& d1, float& d2, float& d3,
                                         unsigned a0, unsigned a1, unsigned a2, unsigned a3,
                                         unsigned b0, unsigned b1) {
    asm volatile(
        "mma.sync.aligned.m16n8k8.row.col.f32.tf32.tf32.f32 "
        "{%0,%1,%2,%3}, {%4,%5,%6,%7}, {%8,%9}, {%0,%1,%2,%3};"
        : "+f"(d0), "+f"(d1), "+f"(d2), "+f"(d3)
        : "r"(a0), "r"(a1), "r"(a2), "r"(a3), "r"(b0), "r"(b1));
}

__device__ __forceinline__ void cp16(unsigned dst_smem, const void* src) {
    asm volatile("cp.async.cg.shared.global [%0], [%1], 16;"
                 :: "r"(dst_smem), "l"(src) : "memory");
}

// ---- prep: v -> tf32 RNA blocked [b][ck][n][kk], vectorized float4 ----
__global__ void __launch_bounds__(256, 4) prep_kernel(const float* __restrict__ v) {
    const int base = blockIdx.x * 256 + threadIdx.x;
    float4 in0 = *reinterpret_cast<const float4*>(v + 4 * (size_t)base);
    float4 in1 = *reinterpret_cast<const float4*>(v + 4 * (size_t)(base + 32768));
    #pragma unroll
    for (int i = 0; i < 2; i++) {
        const int f4 = base + i * 32768;
        const int e  = f4 * 4;
        const int b  = e >> 14, rem = e & 16383;
        const int n  = rem >> 9, k = rem & 511;
        const int ck = k >> 5, kk = k & 31;
        const float4 in = i ? in1 : in0;
        uint4 o = make_uint4(f2tf(in.x), f2tf(in.y), f2tf(in.z), f2tf(in.w));
        *reinterpret_cast<uint4*>(&g_v[(b << 14) + (ck << 10) + (n << 5) + kk]) = o;
    }
}

__global__ void __launch_bounds__(THREADS, 2)
lowrank_kernel(const float* __restrict__ x,
               const float* __restrict__ W,
               float* __restrict__ out)
{
    extern __shared__ unsigned smu[];
    const unsigned sbase = (unsigned)__cvta_generic_to_shared(smu);

    const int tid  = threadIdx.x;
    const int lane = tid & 31;
    const int warp = tid >> 5;
    const int g    = lane >> 2;
    const int t4   = lane & 3;
    const int mw   = warp * 16;

    const int b  = blockIdx.x >> 6;          // 64 tiles per batch
    const int m0 = (blockIdx.x & 63) * TM;

    const float*    xg  = x + ((size_t)b * kN + m0) * kDI;
    const unsigned* gvb = g_v + (size_t)b * (kR * kDI);

    const int vr = tid >> 3, vu = tid & 7;   // v: 256 x 16B units, 1/thread

    auto issue = [&](int c) {
        const int s = c & (STAGES - 1);
        const unsigned xd = sbase + (unsigned)(s * XBUF) * 4u;
        #pragma unroll
        for (int i = 0; i < 4; i++) {
            const int q = tid + 256 * i;     // 1024 x 16B units
            const int r = q >> 3, u = q & 7;
            cp16(xd + (unsigned)(r * XW + u * 4) * 4u,
                 xg + (size_t)r * kDI + c * KC + u * 4);
        }
        const unsigned vd = sbase + (unsigned)(V_OFF + s * VBUF) * 4u;
        cp16(vd + (unsigned)(vr * XW + vu * 4) * 4u,
             gvb + c * (kR * KC) + vr * KC + vu * 4);
        asm volatile("cp.async.commit_group;" ::: "memory");
    };

    issue(0); issue(1); issue(2); issue(3);   // fill all 4 stages

    // ldmatrix per-lane address components (byte offsets within a stage)
    const unsigned a_boff = (unsigned)(mw + (lane & 15)) * 144u
                          + (unsigned)((lane >> 4) * 16);
    const unsigned b_boff = (unsigned)(((lane >> 4) << 3) + (lane & 7)) * 144u
                          + (unsigned)(((lane >> 3) & 1) * 16);

    // ---- GEMM1 mainloop: 2 chunks per synchronization cycle ----
    float acc[4][4] = {};

    for (int cc = 0; cc < NCH; cc += 2) {
        if (cc < NCH - 2) asm volatile("cp.async.wait_group 2;" ::: "memory");
        else              asm volatile("cp.async.wait_group 0;" ::: "memory");
        __syncthreads();   // chunks cc, cc+1 visible to all warps

        #pragma unroll
        for (int d = 0; d < 2; d++) {
            const int c = cc + d;
            const unsigned xa = sbase + (unsigned)((c & 3) * XBUF) * 4u + a_boff;
            const unsigned vb = sbase + (unsigned)((V_OFF + (c & 3) * VBUF)) * 4u + b_boff;
            #pragma unroll
            for (int ks = 0; ks < 4; ks++) {
                unsigned ra0, ra1, ra2, ra3;
                ldsm4(ra0, ra1, ra2, ra3, xa + 32u * ks);
                unsigned a0 = f2tf_u(ra0), a1 = f2tf_u(ra1);
                unsigned a2 = f2tf_u(ra2), a3 = f2tf_u(ra3);
                #pragma unroll
                for (int nbp = 0; nbp < 2; nbp++) {
                    unsigned b00, b01, b10, b11;
                    ldsm4(b00, b01, b10, b11, vb + (unsigned)(nbp * 2304) + 32u * ks);
                    mma_tf32(acc[2*nbp][0],   acc[2*nbp][1],   acc[2*nbp][2],   acc[2*nbp][3],
                             a0, a1, a2, a3, b00, b01);
                    mma_tf32(acc[2*nbp+1][0], acc[2*nbp+1][1], acc[2*nbp+1][2], acc[2*nbp+1][3],
                             a0, a1, a2, a3, b10, b11);
                }
            }
        }
        __syncthreads();   // stages cc&3, (cc+1)&3 fully consumed by all warps

        if (cc + 4 < NCH) { issue(cc + 4); issue(cc + 5); }
    }

    // ---- C1 (128x32 f32) -> smem (stage-0 region), stride 36 words ----
    float* c1 = (float*)smu;
    #pragma unroll
    for (int nb = 0; nb < 4; nb++) {
        *reinterpret_cast<float2*>(&c1[(mw + g)     * XW + nb * 8 + 2 * t4]) =
            make_float2(acc[nb][0], acc[nb][1]);
        *reinterpret_cast<float2*>(&c1[(mw + g + 8) * XW + nb * 8 + 2 * t4]) =
            make_float2(acc[nb][2], acc[nb][3]);
    }
    __syncthreads();

    // ---- GEMM2: relu(C1 @ W^T); warp owns o-cols [warp*64, warp*64+64) ----
    const int oc0 = warp * 64;
    unsigned wf[8][4][2];
    #pragma unroll
    for (int ob = 0; ob < 8; ob++) {
        const float* wr = W + (size_t)(oc0 + ob * 8 + g) * kR;
        #pragma unroll
        for (int ks = 0; ks < 4; ks++) {
            wf[ob][ks][0] = f2tf(wr[ks * 8 + t4]);
            wf[ob][ks][1] = f2tf(wr[ks * 8 + t4 + 4]);
        }
    }

    // warp-private staging buffer: 16 rows x 64 words, XOR-8 swizzled
    float* stg = (float*)smu + STG_OFF + warp * STG_PER_WARP;
    float* ob_ = out + ((size_t)b * kN + m0) * kDO;

    #pragma unroll 1
    for (int mb = 0; mb < TM / 16; mb++) {
        // a-frags from C1 via ldmatrix (rows mb*16 + lane%16, stride 144B)
        const unsigned ca = sbase + (unsigned)(mb * 16 + (lane & 15)) * 144u
                                  + (unsigned)((lane >> 4) * 16);
        unsigned a[4][4];
        #pragma unroll
        for (int ks = 0; ks < 4; ks++) {
            unsigned r0, r1, r2, r3;
            ldsm4(r0, r1, r2, r3, ca + 32u * ks);
            a[ks][0] = f2tf_u(r0); a[ks][1] = f2tf_u(r1);
            a[ks][2] = f2tf_u(r2); a[ks][3] = f2tf_u(r3);
        }
        // compute + stage (STS.64, conflict-free under XOR-8 swizzle)
        const int sw = (g & 3) << 3;                 // same for row g and g+8
        #pragma unroll
        for (int ob = 0; ob < 8; ob++) {
            float d0 = 0.f, d1 = 0.f, d2 = 0.f, d3 = 0.f;
            #pragma unroll
            for (int ks = 0; ks < 4; ks++)
                mma_tf32(d0, d1, d2, d3,
                         a[ks][0], a[ks][1], a[ks][2], a[ks][3],
                         wf[ob][ks][0], wf[ob][ks][1]);
            const int lc = (ob * 8 + 2 * t4) ^ sw;   // XOR keeps 2-word alignment
            *reinterpret_cast<float2*>(&stg[g * 64 + lc]) =
                make_float2(fmaxf(d0, 0.f), fmaxf(d1, 0.f));
            *reinterpret_cast<float2*>(&stg[(g + 8) * 64 + lc]) =
                make_float2(fmaxf(d2, 0.f), fmaxf(d3, 0.f));
        }
        __syncwarp();
        // readback (LDS.128, conflict-free) + full-line STG.128
        const int half = lane >> 4;                  // 0/1
        const int colw = (lane & 15) * 4;            // 0..60
        #pragma unroll
        for (int i = 0; i < 8; i++) {
            const int row = 2 * i + half;
            const int sc  = colw ^ ((row & 3) << 3);
            float4 val = *reinterpret_cast<float4*>(&stg[row * 64 + sc]);
            *reinterpret_cast<float4*>(
                &ob_[(size_t)(mb * 16 + row) * kDO + oc0 + colw]) = val;
        }
        __syncwarp();   // staging reused next mb
    }
}

} // namespace

extern "C" void kernel_launch(void* const* d_in, const int* in_sizes, int n_in,
                              void* d_out, int out_size) {
    (void)in_sizes; (void)n_in; (void)out_size;
    const float* x = (const float*)d_in[0];
    const float* v = (const float*)d_in[1];
    const float* W = (const float*)d_in[2];
    float* out = (float*)d_out;

    prep_kernel<<<128, 256>>>(v);

    cudaFuncSetAttribute(lowrank_kernel,
                         cudaFuncAttributeMaxDynamicSharedMemorySize, SMEM_BYTES);
    lowrank_kernel<<<kB * (kN / TM), THREADS, SMEM_BYTES>>>(x, W, out);
}

// round 17
// speedup vs baseline: 1.2007x; 1.0392x over previous
#include <cuda_runtime.h>
#include <cstdint>
#include <cstddef>

// LowRankINRLayer: out = relu( (x @ v^T) @ W^T )
//   x [16,8192,512] f32, v [16,32,512] f32, W [512,32] f32 -> out f32
//
// Round 17: R14 warp body widened to m=32 per warp (TM=256, 256 threads):
// two a-subtiles share one set of b-fragments, halving per-row barriers,
// v fills and b-side LDSM. x stages XOR-swizzled (unpadded, 128B/row) to fit
// 3 stages + padded v stages in 109.5KB -> 2 CTAs/SM. Epilogue, prep, and all
// numerics identical to R14 (tf32 RNA everywhere, rel_err 4.14e-4).

namespace {

constexpr int kB  = 16;
constexpr int kN  = 8192;
constexpr int kDI = 512;
constexpr int kDO = 512;
constexpr int kR  = 32;

constexpr int TM      = 256;          // rows per CTA
constexpr int KC      = 32;           // K per pipeline chunk
constexpr int NCH     = kDI / KC;     // 16
constexpr int STAGES  = 3;
constexpr int THREADS = 256;          // 8 warps, m=32 each

constexpr int XBUF = TM * KC;                       // 8192 words / stage (32KB, swizzled)
constexpr int VW   = KC + 4;                        // 36 words v row stride (144B)
constexpr int VBUF = kR * VW;                       // 1152 words / stage
constexpr int V_OFF = STAGES * XBUF;                // 24576
constexpr int SMEM_WORDS = V_OFF + STAGES * VBUF;   // 28032
constexpr int SMEM_BYTES = SMEM_WORDS * 4;          // 112128 B -> 2 CTAs/SM

// post-mainloop reuse of x region: C1 (256 x 36 words) then staging
constexpr int C1W = 36;
constexpr int STG_OFF = TM * C1W;                   // word 9216
constexpr int STG_PER_WARP = 16 * 64;               // 1024 words

// tf32(RNA) scratch, filled by prep kernel
__device__ unsigned g_v[kB * kR * kDI];   // blocked [b][ck][n][kk], kk<32

__device__ __forceinline__ unsigned f2tf(float f) {
    unsigned u;
    asm("cvt.rna.tf32.f32 %0, %1;" : "=r"(u) : "f"(f));
    return u;
}
__device__ __forceinline__ unsigned f2tf_u(unsigned raw) {
    return f2tf(__uint_as_float(raw));
}

__device__ __forceinline__ void ldsm4(unsigned& r0, unsigned& r1,
                                      unsigned& r2, unsigned& r3, unsigned a) {
    asm volatile("ldmatrix.sync.aligned.m8n8.x4.shared.b16 {%0,%1,%2,%3}, [%4];"
                 : "=r"(r0), "=r"(r1), "=r"(r2), "=r"(r3) : "r"(a));
}

__device__ __forceinline__ void mma_tf32(float& d0, float& d1, float& d2, float& d3,
                                         unsigned a0, unsigned a1, unsigned a2, unsigned a3,
                                         unsigned b0, unsigned b1) {
    asm volatile(
        "mma.sync.aligned.m16n8k8.row.col.f32.tf32.tf32.f32 "
        "{%0,%1,%2,%3}, {%4,%5,%6,%7}, {%8,%9}, {%0,%1,%2,%3};"
        : "+f"(d0), "+f"(d1), "+f"(d2), "+f"(d3)
        : "r"(a0), "r"(a1), "r"(a2), "r"(a3), "r"(b0), "r"(b1));
}

__device__ __forceinline__ void cp16(unsigned dst_smem, const void* src) {
    asm volatile("cp.async.cg.shared.global [%0], [%1], 16;"
                 :: "r"(dst_smem), "l"(src) : "memory");
}

// ---- prep: v -> tf32 RNA blocked [b][ck][n][kk], vectorized float4 ----
__global__ void __launch_bounds__(256, 4) prep_kernel(const float* __restrict__ v) {
    const int base = blockIdx.x * 256 + threadIdx.x;
    float4 in0 = *reinterpret_cast<const float4*>(v + 4 * (size_t)base);
    float4 in1 = *reinterpret_cast<const float4*>(v + 4 * (size_t)(base + 32768));
    #pragma unroll
    for (int i = 0; i < 2; i++) {
        const int f4 = base + i * 32768;
        const int e  = f4 * 4;
        const int b  = e >> 14, rem = e & 16383;
        const int n  = rem >> 9, k = rem & 511;
        const int ck = k >> 5, kk = k & 31;
        const float4 in = i ? in1 : in0;
        uint4 o = make_uint4(f2tf(in.x), f2tf(in.y), f2tf(in.z), f2tf(in.w));
        *reinterpret_cast<uint4*>(&g_v[(b << 14) + (ck << 10) + (n << 5) + kk]) = o;
    }
}

__global__ void __launch_bounds__(THREADS, 2)
lowrank_kernel(const float* __restrict__ x,
               const float* __restrict__ W,
               float* __restrict__ out)
{
    extern __shared__ unsigned smu[];
    const unsigned sbase = (unsigned)__cvta_generic_to_shared(smu);

    const int tid  = threadIdx.x;
    const int lane = tid & 31;
    const int warp = tid >> 5;
    const int g    = lane >> 2;
    const int t4   = lane & 3;
    const int mw   = warp * 32;              // warp's 32-row block

    const int b  = blockIdx.x >> 5;          // 32 tiles of 256 rows per batch
    const int m0 = (blockIdx.x & 31) * TM;

    const float*    xg  = x + ((size_t)b * kN + m0) * kDI;
    const unsigned* gvb = g_v + (size_t)b * (kR * kDI);

    const int vr = tid >> 3, vu = tid & 7;   // v: 256 x 16B units, 1/thread

    auto issue = [&](int c) {
        const int s = c % STAGES;
        const unsigned xd = sbase + (unsigned)(s * XBUF) * 4u;
        #pragma unroll
        for (int i = 0; i < 8; i++) {
            const int q = tid + 256 * i;     // 2048 x 16B units
            const int r = q >> 3, u = q & 7;
            cp16(xd + (unsigned)(r * 128 + 16 * (u ^ (r & 7))),
                 xg + (size_t)r * kDI + c * KC + u * 4);
        }
        const unsigned vd = sbase + (unsigned)(V_OFF + s * VBUF) * 4u;
        cp16(vd + (unsigned)(vr * VW + vu * 4) * 4u,
             gvb + c * (kR * KC) + vr * KC + vu * 4);
        asm volatile("cp.async.commit_group;" ::: "memory");
    };

    issue(0); issue(1);

    // per-lane fragment address components
    const int a_row  = mw + (lane & 15);     // subtile 0 row; subtile 1 = +16
    const int a_hi   = lane >> 4;            // k-half selector
    const int a_sw   = a_row & 7;            // same for row and row+16
    const unsigned a_base0 = (unsigned)a_row * 128u;          // byte offset
    const unsigned a_base1 = a_base0 + 16u * 128u;
    // v b-frag addressing identical to R14 (padded 144B stride)
    const unsigned b_boff = (unsigned)(((lane >> 4) << 3) + (lane & 7)) * 144u
                          + (unsigned)(((lane >> 3) & 1) * 16);

    // ---- GEMM1 mainloop: per warp m=32, n=32 ----
    float acc[2][4][4] = {};

    for (int c = 0; c < NCH; ++c) {
        if (c < NCH - 1) asm volatile("cp.async.wait_group 1;" ::: "memory");
        else             asm volatile("cp.async.wait_group 0;" ::: "memory");
        __syncthreads();   // chunk c ready; chunk c-1 consumed by all warps

        if (c + 2 < NCH) issue(c + 2);   // stage (c-1)%3 is free now

        const unsigned xs = sbase + (unsigned)((c % STAGES) * XBUF) * 4u;
        const unsigned vb = sbase + (unsigned)(V_OFF + (c % STAGES) * VBUF) * 4u + b_boff;

        #pragma unroll
        for (int ks = 0; ks < 4; ks++) {
            const unsigned ku = 16u * (unsigned)((2 * ks + a_hi) ^ a_sw);
            unsigned p0, p1, p2, p3, q0, q1, q2, q3;
            ldsm4(p0, p1, p2, p3, xs + a_base0 + ku);   // subtile 0 (rows mw..mw+15)
            ldsm4(q0, q1, q2, q3, xs + a_base1 + ku);   // subtile 1 (rows +16)
            unsigned a00 = f2tf_u(p0), a01 = f2tf_u(p1), a02 = f2tf_u(p2), a03 = f2tf_u(p3);
            unsigned a10 = f2tf_u(q0), a11 = f2tf_u(q1), a12 = f2tf_u(q2), a13 = f2tf_u(q3);
            #pragma unroll
            for (int nbp = 0; nbp < 2; nbp++) {
                unsigned b00, b01, b10, b11;   // (b0,b1) for nb=2nbp, 2nbp+1
                ldsm4(b00, b01, b10, b11, vb + (unsigned)(nbp * 2304) + 32u * ks);
                mma_tf32(acc[0][2*nbp][0],   acc[0][2*nbp][1],   acc[0][2*nbp][2],   acc[0][2*nbp][3],
                         a00, a01, a02, a03, b00, b01);
                mma_tf32(acc[0][2*nbp+1][0], acc[0][2*nbp+1][1], acc[0][2*nbp+1][2], acc[0][2*nbp+1][3],
                         a00, a01, a02, a03, b10, b11);
                mma_tf32(acc[1][2*nbp][0],   acc[1][2*nbp][1],   acc[1][2*nbp][2],   acc[1][2*nbp][3],
                         a10, a11, a12, a13, b00, b01);
                mma_tf32(acc[1][2*nbp+1][0], acc[1][2*nbp+1][1], acc[1][2*nbp+1][2], acc[1][2*nbp+1][3],
                         a10, a11, a12, a13, b10, b11);
            }
        }
    }

    // ---- C1 (256x32 f32) -> smem (x region), stride 36 words ----
    __syncthreads();
    float* c1 = (float*)smu;
    #pragma unroll
    for (int at = 0; at < 2; at++) {
        const int rb = mw + at * 16;
        #pragma unroll
        for (int nb = 0; nb < 4; nb++) {
            *reinterpret_cast<float2*>(&c1[(rb + g)     * C1W + nb * 8 + 2 * t4]) =
                make_float2(acc[at][nb][0], acc[at][nb][1]);
            *reinterpret_cast<float2*>(&c1[(rb + g + 8) * C1W + nb * 8 + 2 * t4]) =
                make_float2(acc[at][nb][2], acc[at][nb][3]);
        }
    }
    __syncthreads();

    // ---- GEMM2: relu(C1 @ W^T); warp owns o-cols [warp*64, warp*64+64) ----
    const int oc0 = warp * 64;
    unsigned wf[8][4][2];
    #pragma unroll
    for (int ob = 0; ob < 8; ob++) {
        const float* wr = W + (size_t)(oc0 + ob * 8 + g) * kR;
        #pragma unroll
        for (int ks = 0; ks < 4; ks++) {
            wf[ob][ks][0] = f2tf(wr[ks * 8 + t4]);
            wf[ob][ks][1] = f2tf(wr[ks * 8 + t4 + 4]);
        }
    }

    // warp-private staging buffer: 16 rows x 64 words, XOR-8 swizzled
    float* stg = (float*)smu + STG_OFF + warp * STG_PER_WARP;
    float* ob_ = out + ((size_t)b * kN + m0) * kDO;

    #pragma unroll 1
    for (int mb = 0; mb < TM / 16; mb++) {
        // a-frags from C1 via ldmatrix (rows mb*16 + lane%16, stride 144B)
        const unsigned ca = sbase + (unsigned)(mb * 16 + (lane & 15)) * 144u
                                  + (unsigned)((lane >> 4) * 16);
        unsigned a[4][4];
        #pragma unroll
        for (int ks = 0; ks < 4; ks++) {
            unsigned r0, r1, r2, r3;
            ldsm4(r0, r1, r2, r3, ca + 32u * ks);
            a[ks][0] = f2tf_u(r0); a[ks][1] = f2tf_u(r1);
            a[ks][2] = f2tf_u(r2); a[ks][3] = f2tf_u(r3);
        }
        // compute + stage (STS.64, conflict-free under XOR-8 swizzle)
        const int sw = (g & 3) << 3;                 // same for row g and g+8
        #pragma unroll
        for (int ob = 0; ob < 8; ob++) {
            float d0 = 0.f, d1 = 0.f, d2 = 0.f, d3 = 0.f;
            #pragma unroll
            for (int ks = 0; ks < 4; ks++)
                mma_tf32(d0, d1, d2, d3,
                         a[ks][0], a[ks][1], a[ks][2], a[ks][3],
                         wf[ob][ks][0], wf[ob][ks][1]);
            const int lc = (ob * 8 + 2 * t4) ^ sw;   // XOR keeps 2-word alignment
            *reinterpret_cast<float2*>(&stg[g * 64 + lc]) =
                make_float2(fmaxf(d0, 0.f), fmaxf(d1, 0.f));
            *reinterpret_cast<float2*>(&stg[(g + 8) * 64 + lc]) =
                make_float2(fmaxf(d2, 0.f), fmaxf(d3, 0.f));
        }
        __syncwarp();
        // readback (LDS.128, conflict-free) + full-line STG.128
        const int half = lane >> 4;                  // 0/1
        const int colw = (lane & 15) * 4;            // 0..60
        #pragma unroll
        for (int i = 0; i < 8; i++) {
            const int row = 2 * i + half;
            const int sc  = colw ^ ((row & 3) << 3);
            float4 val = *reinterpret_cast<float4*>(&stg[row * 64 + sc]);
            *reinterpret_cast<float4*>(
                &ob_[(size_t)(mb * 16 + row) * kDO + oc0 + colw]) = val;
        }
        __syncwarp();   // staging reused next mb
    }
}

} // namespace

extern "C" void kernel_launch(void* const* d_in, const int* in_sizes, int n_in,
                              void* d_out, int out_size) {
    (void)in_sizes; (void)n_in; (void)out_size;
    const float* x = (const float*)d_in[0];
    const float* v = (const float*)d_in[1];
    const float* W = (const float*)d_in[2];
    float* out = (float*)d_out;

    prep_kernel<<<128, 256>>>(v);

    cudaFuncSetAttribute(lowrank_kernel,
                         cudaFuncAttributeMaxDynamicSharedMemorySize, SMEM_BYTES);
    lowrank_kernel<<<kB * (kN / TM), THREADS, SMEM_BYTES>>>(x, W, out);
}